// round 7
// baseline (speedup 1.0000x reference)
#include <cuda_runtime.h>
#include <cstdint>
#include <math.h>

#define Bb 4
#define Nn 2048
#define Dd 512
#define Hh 8
#define HD 64
#define Mm (Bb * Nn)   // 8192
#define SC_LOG2E 0.18033688f   // 0.125 * log2(e)

// ---------------- scratch ----------------
__device__ float g_Q[(size_t)Mm * Dd];
__device__ float g_K[(size_t)Mm * Dd];
__device__ float g_V[(size_t)Mm * Dd];
__device__ float g_Hh[(size_t)Mm * Dd];
__device__ float g_Y[(size_t)Mm * Dd];
__device__ float g_Xr[(size_t)Mm * Dd];        // tf32-rounded x
__device__ float g_Wr[4][(size_t)Dd * Dd];     // tf32-rounded Wq,Wk,Wv,Wo

// ---------------- helpers ----------------
__device__ __forceinline__ uint32_t smem_u32(const void* p) {
    uint32_t a;
    asm("{ .reg .u64 t; cvta.to.shared.u64 t, %1; cvt.u32.u64 %0, t; }" : "=r"(a) : "l"(p));
    return a;
}
__device__ __forceinline__ float ex2(float x) {
    float y; asm("ex2.approx.f32 %0, %1;" : "=f"(y) : "f"(x)); return y;
}
__device__ __forceinline__ float tf32r(float f) {
    uint32_t u; asm("cvt.rna.tf32.f32 %0, %1;" : "=r"(u) : "f"(f));
    return __uint_as_float(u);
}
__device__ __forceinline__ void mma_tf32(float* c, const uint32_t* a, const uint32_t* b) {
    asm volatile("mma.sync.aligned.m16n8k8.row.col.f32.tf32.tf32.f32 "
        "{%0,%1,%2,%3}, {%4,%5,%6,%7}, {%8,%9}, {%0,%1,%2,%3};"
        : "+f"(c[0]), "+f"(c[1]), "+f"(c[2]), "+f"(c[3])
        : "r"(a[0]), "r"(a[1]), "r"(a[2]), "r"(a[3]), "r"(b[0]), "r"(b[1]));
}
__device__ __forceinline__ void cpa16(uint32_t dst, const void* src) {
    asm volatile("cp.async.cg.shared.global [%0], [%1], 16;" :: "r"(dst), "l"(src));
}
#define CP_COMMIT() asm volatile("cp.async.commit_group;" ::: "memory")
#define CP_WAIT1()  asm volatile("cp.async.wait_group 1;" ::: "memory")
#define CP_WAIT0()  asm volatile("cp.async.wait_group 0;" ::: "memory")

// ---------------- pre-round kernel (fp32 -> tf32 RNA) ----------------
__global__ void __launch_bounds__(256) round_kernel(
    const float* __restrict__ in, float* __restrict__ out, int n4)
{
    int i = blockIdx.x * 256 + threadIdx.x;
    if (i < n4) {
        float4 v = ((const float4*)in)[i];
        v.x = tf32r(v.x); v.y = tf32r(v.y); v.z = tf32r(v.z); v.w = tf32r(v.w);
        ((float4*)out)[i] = v;
    }
}

// ======================================================================
// tf32 mma GEMM, cp.async double-buffered. Inputs MUST be pre-rounded.
// BM=128, BN=64, BK=32, 256 threads (8 warps 4x2), warp tile 32x32.
// ======================================================================
#define GBM 128
#define GBN 64
#define GBK 32
#define ASTR 36
#define BSTR 68
#define GSM_BUF (GBM * ASTR + GBK * BSTR)   // 6784 floats per buffer
#define GEMM_SMEM_BYTES (2 * GSM_BUF * 4)   // 54272

__global__ void __launch_bounds__(256, 3) gemm_mma_kernel(
    const float* __restrict__ A, const float* __restrict__ W,
    const float* __restrict__ bias, const float* __restrict__ resid,
    float* __restrict__ C, int M, int N, int K, int roundOut)
{
    extern __shared__ __align__(16) float gsm[];
    const uint32_t sbase = smem_u32(gsm);

    const int tid = threadIdx.x;
    const int wid = tid >> 5, lane = tid & 31;
    const int g = lane >> 2, q = lane & 3;
    const int wm = wid & 3, wn = wid >> 2;
    const int m0 = blockIdx.y * GBM;
    const int n0 = blockIdx.x * GBN;
    const int nk = K / GBK;

    const int ar0 = tid >> 3, ac0 = (tid & 7) * 4;   // 32 rows / pass
    const int wr0 = tid >> 4, wc0 = (tid & 15) * 4;  // 16 rows / pass

    auto issue = [&](int kt, int buf) {
        const float* Ab = A + (size_t)m0 * K + kt * GBK;
        const uint32_t as = sbase + (uint32_t)(buf * GSM_BUF) * 4;
        const uint32_t ws = as + (uint32_t)(GBM * ASTR) * 4;
#pragma unroll
        for (int i = 0; i < 4; i++) {
            int r = i * 32 + ar0;
            cpa16(as + (uint32_t)(r * ASTR + ac0) * 4, Ab + (size_t)r * K + ac0);
        }
#pragma unroll
        for (int i = 0; i < 2; i++) {
            int r = i * 16 + wr0;
            cpa16(ws + (uint32_t)(r * BSTR + wc0) * 4, W + (size_t)(kt * GBK + r) * N + n0 + wc0);
        }
        CP_COMMIT();
    };

    float acc[2][4][4];
#pragma unroll
    for (int t = 0; t < 2; t++)
#pragma unroll
        for (int nb = 0; nb < 4; nb++)
#pragma unroll
            for (int i = 0; i < 4; i++) acc[t][nb][i] = 0.f;

    issue(0, 0);

#pragma unroll 1
    for (int kt = 0; kt < nk; kt++) {
        const int buf = kt & 1;
        if (kt + 1 < nk) { issue(kt + 1, buf ^ 1); CP_WAIT1(); }
        else             { CP_WAIT0(); }
        __syncthreads();

        const float* As = gsm + buf * GSM_BUF;
        const float* Ws = As + GBM * ASTR;

#pragma unroll
        for (int kk = 0; kk < 4; kk++) {
            uint32_t a[2][4];
#pragma unroll
            for (int t = 0; t < 2; t++) {
                const float* arp = As + (wm * 32 + 16 * t + g) * ASTR + 8 * kk + q;
                a[t][0] = __float_as_uint(arp[0]);
                a[t][1] = __float_as_uint(arp[8 * ASTR]);
                a[t][2] = __float_as_uint(arp[4]);
                a[t][3] = __float_as_uint(arp[8 * ASTR + 4]);
            }
            uint32_t bf[4][2];
#pragma unroll
            for (int nb = 0; nb < 4; nb++) {
                const float* brp = Ws + (8 * kk + q) * BSTR + wn * 32 + 8 * nb + g;
                bf[nb][0] = __float_as_uint(brp[0]);
                bf[nb][1] = __float_as_uint(brp[4 * BSTR]);
            }
#pragma unroll
            for (int t = 0; t < 2; t++)
#pragma unroll
                for (int nb = 0; nb < 4; nb++)
                    mma_tf32(acc[t][nb], a[t], bf[nb]);
        }
        __syncthreads();
    }

    // ---- epilogue ----
#pragma unroll
    for (int t = 0; t < 2; t++) {
        const int r0 = m0 + wm * 32 + 16 * t + g;
#pragma unroll
        for (int nb = 0; nb < 4; nb++) {
            const int c = n0 + wn * 32 + 8 * nb + 2 * q;
            float bx = bias[c], by = bias[c + 1];
            float2 w0, w1;
            w0.x = acc[t][nb][0] + bx; w0.y = acc[t][nb][1] + by;
            w1.x = acc[t][nb][2] + bx; w1.y = acc[t][nb][3] + by;
            if (resid) {
                float2 r4 = *(const float2*)(resid + (size_t)r0 * N + c);
                float2 r5 = *(const float2*)(resid + (size_t)(r0 + 8) * N + c);
                w0.x += r4.x; w0.y += r4.y;
                w1.x += r5.x; w1.y += r5.y;
            }
            if (roundOut) {
                w0.x = tf32r(w0.x); w0.y = tf32r(w0.y);
                w1.x = tf32r(w1.x); w1.y = tf32r(w1.y);
            }
            *(float2*)(C + (size_t)r0 * N + c) = w0;
            *(float2*)(C + (size_t)(r0 + 8) * N + c) = w1;
        }
    }
}

// ======================================================================
// mma.sync tf32 attention: cp.async double-buffered K/V, shfl P-frags.
// Q/K/V pre-rounded to tf32 by producer. Output H rounded to tf32.
// ======================================================================
#define STR 68
#define OFF_Q 0
#define OFF_KB(buf) (128 * STR + (buf) * 2 * 64 * STR)
#define OFF_VB(buf) (OFF_KB(buf) + 64 * STR)
#define ATTN_SMEM_FLOATS (128 * STR + 4 * 64 * STR)   // 26112
#define ATTN_SMEM_BYTES (ATTN_SMEM_FLOATS * 4)        // 104448

__global__ void __launch_bounds__(128, 2) attn_mma_kernel(
    const float* __restrict__ Q, const float* __restrict__ K,
    const float* __restrict__ V, const int* __restrict__ adj,
    float* __restrict__ O)
{
    extern __shared__ __align__(16) float sm[];
    const uint32_t sbase = smem_u32(sm);
    const int tid = threadIdx.x;
    const int wid = tid >> 5, lane = tid & 31;
    const int g = lane >> 2, q = lane & 3;
    const int h = blockIdx.y, b = blockIdx.z;
    const int q0 = blockIdx.x * 128;
    const unsigned FULL = 0xffffffffu;

    const int fr = tid >> 4, fc = (tid & 15) * 4;   // 8 rows per 128-thread pass

    // ---- prologue: Q tile 128 rows (group 0) ----
    {
        const float* qg = Q + ((size_t)(b * Nn + q0)) * Dd + h * HD;
#pragma unroll
        for (int i = 0; i < 16; i++) {
            int r = i * 8 + fr;
            cpa16(sbase + (uint32_t)(OFF_Q + r * STR + fc) * 4, qg + (size_t)r * Dd + fc);
        }
        CP_COMMIT();
    }
    // ---- tile 0 K/V: 64 rows each (group 1) ----
    {
        const float* kg = K + ((size_t)(b * Nn)) * Dd + h * HD;
        const float* vg = V + ((size_t)(b * Nn)) * Dd + h * HD;
#pragma unroll
        for (int i = 0; i < 8; i++) {
            int r = i * 8 + fr;
            cpa16(sbase + (uint32_t)(OFF_KB(0) + r * STR + fc) * 4, kg + (size_t)r * Dd + fc);
            cpa16(sbase + (uint32_t)(OFF_VB(0) + r * STR + fc) * 4, vg + (size_t)r * Dd + fc);
        }
        CP_COMMIT();
    }

    float oacc[2][8][4];
#pragma unroll
    for (int t = 0; t < 2; t++)
#pragma unroll
        for (int n = 0; n < 8; n++)
#pragma unroll
            for (int i = 0; i < 4; i++) oacc[t][n][i] = 0.f;
    float lacc[4] = {0.f, 0.f, 0.f, 0.f};

    const int srcA = (lane & 28) | (q >> 1);
    const int srcB = srcA | 2;
    const bool odd = q & 1;

#pragma unroll 1
    for (int t64 = 0; t64 < 32; t64++) {
        const int buf = t64 & 1;
        const int k0 = t64 * 64;

        if (t64 + 1 < 32) {
            const float* kg = K + ((size_t)(b * Nn + k0 + 64)) * Dd + h * HD;
            const float* vg = V + ((size_t)(b * Nn + k0 + 64)) * Dd + h * HD;
            const int ob = buf ^ 1;
#pragma unroll
            for (int i = 0; i < 8; i++) {
                int r = i * 8 + fr;
                cpa16(sbase + (uint32_t)(OFF_KB(ob) + r * STR + fc) * 4, kg + (size_t)r * Dd + fc);
                cpa16(sbase + (uint32_t)(OFF_VB(ob) + r * STR + fc) * 4, vg + (size_t)r * Dd + fc);
            }
            CP_COMMIT();
            CP_WAIT1();
        } else {
            CP_WAIT0();
        }
        __syncthreads();

        const float* Ks = sm + OFF_KB(buf);
        const float* Vs = sm + OFF_VB(buf);

        // ---- S = Q(32x64) @ K^T(64x64) per warp ----
        float sacc[2][8][4];
#pragma unroll
        for (int t = 0; t < 2; t++)
#pragma unroll
            for (int n = 0; n < 8; n++)
#pragma unroll
                for (int i = 0; i < 4; i++) sacc[t][n][i] = 0.f;

#pragma unroll
        for (int kk = 0; kk < 8; kk++) {
            uint32_t a[2][4];
#pragma unroll
            for (int t = 0; t < 2; t++) {
                const float* qrow = sm + OFF_Q + (wid * 32 + 16 * t + g) * STR + 8 * kk + q;
                a[t][0] = __float_as_uint(qrow[0]);
                a[t][1] = __float_as_uint(qrow[8 * STR]);
                a[t][2] = __float_as_uint(qrow[4]);
                a[t][3] = __float_as_uint(qrow[8 * STR + 4]);
            }
            uint32_t bf[8][2];
#pragma unroll
            for (int n = 0; n < 8; n++) {
                const float* krow = Ks + (8 * n + g) * STR + 8 * kk + q;
                bf[n][0] = __float_as_uint(krow[0]);
                bf[n][1] = __float_as_uint(krow[4]);
            }
#pragma unroll
            for (int t = 0; t < 2; t++)
#pragma unroll
                for (int n = 0; n < 8; n++)
                    mma_tf32(sacc[t][n], a[t], bf[n]);
        }

        // ---- softmax in place: P = mask * exp2(S*sc), tf32-rounded ----
#pragma unroll
        for (int t = 0; t < 2; t++) {
            const int rloc = 16 * t + g;
            const size_t arow = (size_t)(b * Nn + q0 + wid * 32 + rloc) * Nn + k0;
            const int* a0p = adj + arow;
            const int* a1p = adj + arow + (size_t)8 * Nn;
            float l01 = 0.f, l23 = 0.f;
#pragma unroll
            for (int n = 0; n < 8; n++) {
                int2 m0 = *(const int2*)(a0p + 8 * n + 2 * q);
                int2 m1 = *(const int2*)(a1p + 8 * n + 2 * q);
                float p0 = m0.x ? tf32r(ex2(sacc[t][n][0] * SC_LOG2E)) : 0.f;
                float p1 = m0.y ? tf32r(ex2(sacc[t][n][1] * SC_LOG2E)) : 0.f;
                float p2 = m1.x ? tf32r(ex2(sacc[t][n][2] * SC_LOG2E)) : 0.f;
                float p3 = m1.y ? tf32r(ex2(sacc[t][n][3] * SC_LOG2E)) : 0.f;
                sacc[t][n][0] = p0; sacc[t][n][1] = p1;
                sacc[t][n][2] = p2; sacc[t][n][3] = p3;
                l01 += p0 + p1; l23 += p2 + p3;
            }
            lacc[2 * t + 0] += l01;
            lacc[2 * t + 1] += l23;
        }

        // ---- O += P(32x64) @ V(64x64); P a-frags via shfl from C-layout ----
#pragma unroll
        for (int kk = 0; kk < 8; kk++) {
            uint32_t a[2][4];
#pragma unroll
            for (int t = 0; t < 2; t++) {
                float p0 = sacc[t][kk][0], p1 = sacc[t][kk][1];
                float p2 = sacc[t][kk][2], p3 = sacc[t][kk][3];
                float u0 = __shfl_sync(FULL, p0, srcA), u1 = __shfl_sync(FULL, p1, srcA);
                float u2 = __shfl_sync(FULL, p0, srcB), u3 = __shfl_sync(FULL, p1, srcB);
                float v0 = __shfl_sync(FULL, p2, srcA), v1 = __shfl_sync(FULL, p3, srcA);
                float v2 = __shfl_sync(FULL, p2, srcB), v3 = __shfl_sync(FULL, p3, srcB);
                a[t][0] = __float_as_uint(odd ? u1 : u0);
                a[t][1] = __float_as_uint(odd ? v1 : v0);
                a[t][2] = __float_as_uint(odd ? u3 : u2);
                a[t][3] = __float_as_uint(odd ? v3 : v2);
            }
            uint32_t bf[8][2];
#pragma unroll
            for (int n = 0; n < 8; n++) {
                const float* vrow = Vs + (8 * kk + q) * STR + 8 * n + g;
                bf[n][0] = __float_as_uint(vrow[0]);
                bf[n][1] = __float_as_uint(vrow[4 * STR]);
            }
#pragma unroll
            for (int t = 0; t < 2; t++)
#pragma unroll
                for (int n = 0; n < 8; n++)
                    mma_tf32(oacc[t][n], a[t], bf[n]);
        }
        __syncthreads();
    }

    // ---- row-sum reduce across quad, write H (tf32-rounded) ----
#pragma unroll
    for (int i = 0; i < 4; i++) {
        lacc[i] += __shfl_xor_sync(FULL, lacc[i], 1);
        lacc[i] += __shfl_xor_sync(FULL, lacc[i], 2);
    }
    float inv[4];
#pragma unroll
    for (int i = 0; i < 4; i++) inv[i] = 1.f / lacc[i];

    float* og = O + ((size_t)(b * Nn + q0 + wid * 32)) * Dd + h * HD;
#pragma unroll
    for (int t = 0; t < 2; t++) {
        const int rloc = 16 * t + g;
#pragma unroll
        for (int n = 0; n < 8; n++) {
            float2 w0;
            w0.x = tf32r(oacc[t][n][0] * inv[2 * t]);
            w0.y = tf32r(oacc[t][n][1] * inv[2 * t]);
            *(float2*)(og + (size_t)rloc * Dd + 8 * n + 2 * q) = w0;
            float2 w1;
            w1.x = tf32r(oacc[t][n][2] * inv[2 * t + 1]);
            w1.y = tf32r(oacc[t][n][3] * inv[2 * t + 1]);
            *(float2*)(og + (size_t)(rloc + 8) * Dd + 8 * n + 2 * q) = w1;
        }
    }
}

// ================= LayerNorm (unchanged) =================
__global__ __launch_bounds__(128) void ln_kernel(
    const float* __restrict__ Y, const float* __restrict__ gamma,
    const float* __restrict__ beta, float* __restrict__ out)
{
    __shared__ float sbuf[4];
    __shared__ float smu, srstd;
    const int tid = threadIdx.x;
    const int row = blockIdx.x;
    const float* y = Y + (size_t)row * Dd;

    float4 v = ((const float4*)y)[tid];
    float sum = v.x + v.y + v.z + v.w;
    int lane = tid & 31, wid = tid >> 5;
#pragma unroll
    for (int off = 16; off > 0; off >>= 1) sum += __shfl_xor_sync(0xffffffffu, sum, off);
    if (lane == 0) sbuf[wid] = sum;
    __syncthreads();
    if (tid == 0) smu = (sbuf[0] + sbuf[1] + sbuf[2] + sbuf[3]) * (1.f / Dd);
    __syncthreads();
    float mu = smu;

    float dx = v.x - mu, dy = v.y - mu, dz = v.z - mu, dw = v.w - mu;
    float sq = dx * dx + dy * dy + dz * dz + dw * dw;
#pragma unroll
    for (int off = 16; off > 0; off >>= 1) sq += __shfl_xor_sync(0xffffffffu, sq, off);
    __syncthreads();
    if (lane == 0) sbuf[wid] = sq;
    __syncthreads();
    if (tid == 0) {
        float var = (sbuf[0] + sbuf[1] + sbuf[2] + sbuf[3]) * (1.f / Dd);
        srstd = rsqrtf(var + 1e-5f);
    }
    __syncthreads();
    float rstd = srstd;

    int c = tid * 4;
    float4 g = *(const float4*)(gamma + c);
    float4 be = *(const float4*)(beta + c);
    float4 r;
    r.x = dx * rstd * g.x + be.x;
    r.y = dy * rstd * g.y + be.y;
    r.z = dz * rstd * g.z + be.z;
    r.w = dw * rstd * g.w + be.w;
    ((float4*)(out + (size_t)row * Dd))[tid] = r;
}

// ================= launch =================
extern "C" void kernel_launch(void* const* d_in, const int* in_sizes, int n_in,
                              void* d_out, int out_size)
{
    const float* x     = (const float*)d_in[0];
    const int*   adj   = (const int*)d_in[1];
    const float* Wq    = (const float*)d_in[2];
    const float* bq    = (const float*)d_in[3];
    const float* Wk    = (const float*)d_in[4];
    const float* bk    = (const float*)d_in[5];
    const float* Wv    = (const float*)d_in[6];
    const float* bv    = (const float*)d_in[7];
    const float* Wo    = (const float*)d_in[8];
    const float* bo    = (const float*)d_in[9];
    const float* gamma = (const float*)d_in[10];
    const float* beta  = (const float*)d_in[11];
    float* out = (float*)d_out;

    float *Qb, *Kb, *Vb, *Hb, *Yb, *Xr, *Wr;
    cudaGetSymbolAddress((void**)&Qb, g_Q);
    cudaGetSymbolAddress((void**)&Kb, g_K);
    cudaGetSymbolAddress((void**)&Vb, g_V);
    cudaGetSymbolAddress((void**)&Hb, g_Hh);
    cudaGetSymbolAddress((void**)&Yb, g_Y);
    cudaGetSymbolAddress((void**)&Xr, g_Xr);
    cudaGetSymbolAddress((void**)&Wr, g_Wr);
    float* Wr0 = Wr;
    float* Wr1 = Wr + (size_t)Dd * Dd;
    float* Wr2 = Wr + (size_t)2 * Dd * Dd;
    float* Wr3 = Wr + (size_t)3 * Dd * Dd;

    cudaFuncSetAttribute(attn_mma_kernel, cudaFuncAttributeMaxDynamicSharedMemorySize, ATTN_SMEM_BYTES);
    cudaFuncSetAttribute(gemm_mma_kernel, cudaFuncAttributeMaxDynamicSharedMemorySize, GEMM_SMEM_BYTES);

    // pre-round inputs to tf32 (RNA)
    round_kernel<<<(Mm * Dd / 4 + 255) / 256, 256>>>(x, Xr, Mm * Dd / 4);
    round_kernel<<<(Dd * Dd / 4 + 255) / 256, 256>>>(Wq, Wr0, Dd * Dd / 4);
    round_kernel<<<(Dd * Dd / 4 + 255) / 256, 256>>>(Wk, Wr1, Dd * Dd / 4);
    round_kernel<<<(Dd * Dd / 4 + 255) / 256, 256>>>(Wv, Wr2, Dd * Dd / 4);
    round_kernel<<<(Dd * Dd / 4 + 255) / 256, 256>>>(Wo, Wr3, Dd * Dd / 4);

    dim3 ggrid(Dd / GBN, Mm / GBM);   // (8, 64)
    gemm_mma_kernel<<<ggrid, 256, GEMM_SMEM_BYTES>>>(Xr, Wr0, bq, nullptr, Qb, Mm, Dd, Dd, 1);
    gemm_mma_kernel<<<ggrid, 256, GEMM_SMEM_BYTES>>>(Xr, Wr1, bk, nullptr, Kb, Mm, Dd, Dd, 1);
    gemm_mma_kernel<<<ggrid, 256, GEMM_SMEM_BYTES>>>(Xr, Wr2, bv, nullptr, Vb, Mm, Dd, Dd, 1);

    dim3 agrid(Nn / 128, Hh, Bb);     // (16, 8, 4)
    attn_mma_kernel<<<agrid, 128, ATTN_SMEM_BYTES>>>(Qb, Kb, Vb, adj, Hb);

    gemm_mma_kernel<<<ggrid, 256, GEMM_SMEM_BYTES>>>(Hb, Wr3, bo, x, Yb, Mm, Dd, Dd, 0);

    ln_kernel<<<Mm, 128>>>(Yb, gamma, beta, out);
}

// round 8
// speedup vs baseline: 1.3350x; 1.3350x over previous
#include <cuda_runtime.h>
#include <cstdint>
#include <math.h>

#define Bb 4
#define Nn 2048
#define Dd 512
#define Hh 8
#define HD 64
#define Mm (Bb * Nn)   // 8192
#define SC_LOG2E 0.18033688f   // 0.125 * log2(e)

// ---------------- scratch ----------------
__device__ float g_Q[(size_t)Mm * Dd];
__device__ float g_K[(size_t)Mm * Dd];
__device__ float g_V[(size_t)Mm * Dd];
__device__ float g_Hh[(size_t)Mm * Dd];
__device__ float g_Y[(size_t)Mm * Dd];

// ---------------- helpers ----------------
__device__ __forceinline__ float ex2(float x) {
    float y; asm("ex2.approx.f32 %0, %1;" : "=f"(y) : "f"(x)); return y;
}
__device__ __forceinline__ float tf32r(float f) {
    uint32_t u; asm("cvt.rna.tf32.f32 %0, %1;" : "=r"(u) : "f"(f));
    return __uint_as_float(u);
}
__device__ __forceinline__ void mma_tf32(float* c, const uint32_t* a, const uint32_t* b) {
    asm volatile("mma.sync.aligned.m16n8k8.row.col.f32.tf32.tf32.f32 "
        "{%0,%1,%2,%3}, {%4,%5,%6,%7}, {%8,%9}, {%0,%1,%2,%3};"
        : "+f"(c[0]), "+f"(c[1]), "+f"(c[2]), "+f"(c[3])
        : "r"(a[0]), "r"(a[1]), "r"(a[2]), "r"(a[3]), "r"(b[0]), "r"(b[1]));
}

// ======================================================================
// tf32 mma GEMM (R5 measured-good version, unchanged)
// BM=128, BN=64, BK=32, 256 threads (8 warps 4x2), warp tile 32x32.
// ======================================================================
#define GBM 128
#define GBN 64
#define GBK 32
#define ASTR 36
#define BSTR 68

__global__ void __launch_bounds__(256, 3) gemm_mma_kernel(
    const float* __restrict__ A, const float* __restrict__ W,
    const float* __restrict__ bias, const float* __restrict__ resid,
    float* __restrict__ C, int M, int N, int K)
{
    __shared__ __align__(16) float As[GBM * ASTR];   // [m][k]
    __shared__ __align__(16) float Ws[GBK * BSTR];   // [k][n]

    const int tid = threadIdx.x;
    const int wid = tid >> 5, lane = tid & 31;
    const int g = lane >> 2, q = lane & 3;
    const int wm = wid & 3, wn = wid >> 2;
    const int m0 = blockIdx.y * GBM;
    const int n0 = blockIdx.x * GBN;

    float acc[2][4][4];
#pragma unroll
    for (int t = 0; t < 2; t++)
#pragma unroll
        for (int nb = 0; nb < 4; nb++)
#pragma unroll
            for (int i = 0; i < 4; i++) acc[t][nb][i] = 0.f;

    for (int k0 = 0; k0 < K; k0 += GBK) {
#pragma unroll
        for (int i = 0; i < 4; i++) {
            int idx = i * 256 + tid;
            int r = idx >> 3, c4 = (idx & 7) * 4;
            float4 a4 = *(const float4*)(A + (size_t)(m0 + r) * K + k0 + c4);
            float* d = As + r * ASTR + c4;
            d[0] = tf32r(a4.x); d[1] = tf32r(a4.y);
            d[2] = tf32r(a4.z); d[3] = tf32r(a4.w);
        }
#pragma unroll
        for (int i = 0; i < 2; i++) {
            int idx = i * 256 + tid;
            int r = idx >> 4, c4 = (idx & 15) * 4;
            float4 w4 = *(const float4*)(W + (size_t)(k0 + r) * N + n0 + c4);
            float* d = Ws + r * BSTR + c4;
            d[0] = tf32r(w4.x); d[1] = tf32r(w4.y);
            d[2] = tf32r(w4.z); d[3] = tf32r(w4.w);
        }
        __syncthreads();

#pragma unroll
        for (int kk = 0; kk < 4; kk++) {
            uint32_t a[2][4];
#pragma unroll
            for (int t = 0; t < 2; t++) {
                const float* ar = As + (wm * 32 + 16 * t + g) * ASTR + 8 * kk + q;
                a[t][0] = __float_as_uint(ar[0]);
                a[t][1] = __float_as_uint(ar[8 * ASTR]);
                a[t][2] = __float_as_uint(ar[4]);
                a[t][3] = __float_as_uint(ar[8 * ASTR + 4]);
            }
            uint32_t bf[4][2];
#pragma unroll
            for (int nb = 0; nb < 4; nb++) {
                const float* br = Ws + (8 * kk + q) * BSTR + wn * 32 + 8 * nb + g;
                bf[nb][0] = __float_as_uint(br[0]);
                bf[nb][1] = __float_as_uint(br[4 * BSTR]);
            }
#pragma unroll
            for (int t = 0; t < 2; t++)
#pragma unroll
                for (int nb = 0; nb < 4; nb++)
                    mma_tf32(acc[t][nb], a[t], bf[nb]);
        }
        __syncthreads();
    }

#pragma unroll
    for (int t = 0; t < 2; t++) {
        const int r0 = m0 + wm * 32 + 16 * t + g;
#pragma unroll
        for (int nb = 0; nb < 4; nb++) {
            const int c = n0 + wn * 32 + 8 * nb + 2 * q;
            float bx = bias[c], by = bias[c + 1];
            float2 w0, w1;
            w0.x = acc[t][nb][0] + bx; w0.y = acc[t][nb][1] + by;
            w1.x = acc[t][nb][2] + bx; w1.y = acc[t][nb][3] + by;
            if (resid) {
                float2 r4 = *(const float2*)(resid + (size_t)r0 * N + c);
                float2 r5 = *(const float2*)(resid + (size_t)(r0 + 8) * N + c);
                w0.x += r4.x; w0.y += r4.y;
                w1.x += r5.x; w1.y += r5.y;
            }
            *(float2*)(C + (size_t)r0 * N + c) = w0;
            *(float2*)(C + (size_t)(r0 + 8) * N + c) = w1;
        }
    }
}

// ======================================================================
// mma.sync tf32 attention: 64 queries/CTA, 16 queries/warp, 3 CTAs/SM.
// grid (32 q-tiles, 8 heads, 4 batch), 128 threads (4 warps).
// ======================================================================
#define STR 68
#define OFF_Q 0
#define OFF_K (64 * STR)
#define OFF_V (128 * STR)
#define OFF_P (192 * STR)
#define ATTN_SMEM_FLOATS (256 * STR)            // 17408
#define ATTN_SMEM_BYTES (ATTN_SMEM_FLOATS * 4)  // 69632

__global__ void __launch_bounds__(128, 3) attn_mma_kernel(
    const float* __restrict__ Q, const float* __restrict__ K,
    const float* __restrict__ V, const int* __restrict__ adj,
    float* __restrict__ O)
{
    extern __shared__ __align__(16) float sm[];
    const int tid = threadIdx.x;
    const int wid = tid >> 5, lane = tid & 31;
    const int g = lane >> 2, q = lane & 3;
    const int h = blockIdx.y, b = blockIdx.z;
    const int q0 = blockIdx.x * 64;
    const unsigned FULL = 0xffffffffu;

    // ---- stage Q tile (64 x 64), tf32-rounded ----
    {
        const float* qg = Q + ((size_t)(b * Nn + q0)) * Dd + h * HD;
#pragma unroll
        for (int i = 0; i < 8; i++) {
            int f = i * 128 + tid, r = f >> 4, c = (f & 15) * 4;
            float4 v4 = *(const float4*)(qg + (size_t)r * Dd + c);
            float* dst = sm + OFF_Q + r * STR + c;
            dst[0] = tf32r(v4.x); dst[1] = tf32r(v4.y);
            dst[2] = tf32r(v4.z); dst[3] = tf32r(v4.w);
        }
    }
    __syncthreads();

    float oacc[8][4];
#pragma unroll
    for (int n = 0; n < 8; n++)
#pragma unroll
        for (int i = 0; i < 4; i++) oacc[n][i] = 0.f;
    float lacc[2] = {0.f, 0.f};   // rows g, g+8 of the warp's 16-row tile

    float* Pw = sm + OFF_P + wid * 16 * STR;
    const float* Ks = sm + OFF_K;
    const float* Vs = sm + OFF_V;

#pragma unroll 1
    for (int t64 = 0; t64 < 32; t64++) {
        const int k0 = t64 * 64;
        __syncthreads();
        // ---- stage K, V tiles (64 x 64), tf32-rounded ----
        {
            const float* kg = K + ((size_t)(b * Nn + k0)) * Dd + h * HD;
            const float* vg = V + ((size_t)(b * Nn + k0)) * Dd + h * HD;
#pragma unroll
            for (int i = 0; i < 8; i++) {
                int f = i * 128 + tid, r = f >> 4, c = (f & 15) * 4;
                float4 kv = *(const float4*)(kg + (size_t)r * Dd + c);
                float* kd = sm + OFF_K + r * STR + c;
                kd[0] = tf32r(kv.x); kd[1] = tf32r(kv.y);
                kd[2] = tf32r(kv.z); kd[3] = tf32r(kv.w);
                float4 vv = *(const float4*)(vg + (size_t)r * Dd + c);
                float* vd = sm + OFF_V + r * STR + c;
                vd[0] = tf32r(vv.x); vd[1] = tf32r(vv.y);
                vd[2] = tf32r(vv.z); vd[3] = tf32r(vv.w);
            }
        }
        __syncthreads();

        // ---- S = Q(16x64) @ K^T(64x64) per warp: 64 mma ----
        float sacc[8][4];
#pragma unroll
        for (int n = 0; n < 8; n++)
#pragma unroll
            for (int i = 0; i < 4; i++) sacc[n][i] = 0.f;

#pragma unroll
        for (int kk = 0; kk < 8; kk++) {
            uint32_t a[4];
            {
                const float* qrow = sm + OFF_Q + (wid * 16 + g) * STR + 8 * kk + q;
                a[0] = __float_as_uint(qrow[0]);
                a[1] = __float_as_uint(qrow[8 * STR]);
                a[2] = __float_as_uint(qrow[4]);
                a[3] = __float_as_uint(qrow[8 * STR + 4]);
            }
            uint32_t bf[8][2];
#pragma unroll
            for (int n = 0; n < 8; n++) {
                const float* krow = Ks + (8 * n + g) * STR + 8 * kk + q;
                bf[n][0] = __float_as_uint(krow[0]);
                bf[n][1] = __float_as_uint(krow[4]);
            }
#pragma unroll
            for (int n = 0; n < 8; n++)
                mma_tf32(sacc[n], a, bf[n]);
        }

        // ---- softmax: P = mask * exp2(S*sc); row sums; store P to SMEM ----
        {
            const size_t arow = (size_t)(b * Nn + q0 + wid * 16 + g) * Nn + k0;
            const int* a0p = adj + arow;                     // row g
            const int* a1p = adj + arow + (size_t)8 * Nn;    // row g+8
            float l0 = 0.f, l1 = 0.f;
#pragma unroll
            for (int n = 0; n < 8; n++) {
                int2 m0 = *(const int2*)(a0p + 8 * n + 2 * q);
                int2 m1 = *(const int2*)(a1p + 8 * n + 2 * q);
                float p0 = m0.x ? tf32r(ex2(sacc[n][0] * SC_LOG2E)) : 0.f;
                float p1 = m0.y ? tf32r(ex2(sacc[n][1] * SC_LOG2E)) : 0.f;
                float p2 = m1.x ? tf32r(ex2(sacc[n][2] * SC_LOG2E)) : 0.f;
                float p3 = m1.y ? tf32r(ex2(sacc[n][3] * SC_LOG2E)) : 0.f;
                l0 += p0 + p1; l1 += p2 + p3;
                float2 w0; w0.x = p0; w0.y = p1;
                float2 w1; w1.x = p2; w1.y = p3;
                *(float2*)(Pw + g * STR + 8 * n + 2 * q) = w0;
                *(float2*)(Pw + (g + 8) * STR + 8 * n + 2 * q) = w1;
            }
            lacc[0] += l0;
            lacc[1] += l1;
        }
        __syncwarp();

        // ---- O += P(16x64) @ V(64x64): 64 mma ----
#pragma unroll
        for (int kk = 0; kk < 8; kk++) {
            uint32_t a[4];
            {
                const float* prow = Pw + g * STR + 8 * kk + q;
                a[0] = __float_as_uint(prow[0]);
                a[1] = __float_as_uint(prow[8 * STR]);
                a[2] = __float_as_uint(prow[4]);
                a[3] = __float_as_uint(prow[8 * STR + 4]);
            }
            uint32_t bf[8][2];
#pragma unroll
            for (int n = 0; n < 8; n++) {
                const float* vrow = Vs + (8 * kk + q) * STR + 8 * n + g;
                bf[n][0] = __float_as_uint(vrow[0]);
                bf[n][1] = __float_as_uint(vrow[4 * STR]);
            }
#pragma unroll
            for (int n = 0; n < 8; n++)
                mma_tf32(oacc[n], a, bf[n]);
        }
        __syncwarp();
    }

    // ---- reduce row sums across the quad (lanes sharing g) ----
#pragma unroll
    for (int i = 0; i < 2; i++) {
        lacc[i] += __shfl_xor_sync(FULL, lacc[i], 1);
        lacc[i] += __shfl_xor_sync(FULL, lacc[i], 2);
    }
    const float inv0 = 1.f / lacc[0];
    const float inv1 = 1.f / lacc[1];

    // ---- write O ----
    float* og = O + ((size_t)(b * Nn + q0 + wid * 16)) * Dd + h * HD;
#pragma unroll
    for (int n = 0; n < 8; n++) {
        float2 w0;
        w0.x = oacc[n][0] * inv0;
        w0.y = oacc[n][1] * inv0;
        *(float2*)(og + (size_t)g * Dd + 8 * n + 2 * q) = w0;
        float2 w1;
        w1.x = oacc[n][2] * inv1;
        w1.y = oacc[n][3] * inv1;
        *(float2*)(og + (size_t)(g + 8) * Dd + 8 * n + 2 * q) = w1;
    }
}

// ================= LayerNorm (unchanged) =================
__global__ __launch_bounds__(128) void ln_kernel(
    const float* __restrict__ Y, const float* __restrict__ gamma,
    const float* __restrict__ beta, float* __restrict__ out)
{
    __shared__ float sbuf[4];
    __shared__ float smu, srstd;
    const int tid = threadIdx.x;
    const int row = blockIdx.x;
    const float* y = Y + (size_t)row * Dd;

    float4 v = ((const float4*)y)[tid];
    float sum = v.x + v.y + v.z + v.w;
    int lane = tid & 31, wid = tid >> 5;
#pragma unroll
    for (int off = 16; off > 0; off >>= 1) sum += __shfl_xor_sync(0xffffffffu, sum, off);
    if (lane == 0) sbuf[wid] = sum;
    __syncthreads();
    if (tid == 0) smu = (sbuf[0] + sbuf[1] + sbuf[2] + sbuf[3]) * (1.f / Dd);
    __syncthreads();
    float mu = smu;

    float dx = v.x - mu, dy = v.y - mu, dz = v.z - mu, dw = v.w - mu;
    float sq = dx * dx + dy * dy + dz * dz + dw * dw;
#pragma unroll
    for (int off = 16; off > 0; off >>= 1) sq += __shfl_xor_sync(0xffffffffu, sq, off);
    __syncthreads();
    if (lane == 0) sbuf[wid] = sq;
    __syncthreads();
    if (tid == 0) {
        float var = (sbuf[0] + sbuf[1] + sbuf[2] + sbuf[3]) * (1.f / Dd);
        srstd = rsqrtf(var + 1e-5f);
    }
    __syncthreads();
    float rstd = srstd;

    int c = tid * 4;
    float4 g = *(const float4*)(gamma + c);
    float4 be = *(const float4*)(beta + c);
    float4 r;
    r.x = dx * rstd * g.x + be.x;
    r.y = dy * rstd * g.y + be.y;
    r.z = dz * rstd * g.z + be.z;
    r.w = dw * rstd * g.w + be.w;
    ((float4*)(out + (size_t)row * Dd))[tid] = r;
}

// ================= launch =================
extern "C" void kernel_launch(void* const* d_in, const int* in_sizes, int n_in,
                              void* d_out, int out_size)
{
    const float* x     = (const float*)d_in[0];
    const int*   adj   = (const int*)d_in[1];
    const float* Wq    = (const float*)d_in[2];
    const float* bq    = (const float*)d_in[3];
    const float* Wk    = (const float*)d_in[4];
    const float* bk    = (const float*)d_in[5];
    const float* Wv    = (const float*)d_in[6];
    const float* bv    = (const float*)d_in[7];
    const float* Wo    = (const float*)d_in[8];
    const float* bo    = (const float*)d_in[9];
    const float* gamma = (const float*)d_in[10];
    const float* beta  = (const float*)d_in[11];
    float* out = (float*)d_out;

    float *Qb, *Kb, *Vb, *Hb, *Yb;
    cudaGetSymbolAddress((void**)&Qb, g_Q);
    cudaGetSymbolAddress((void**)&Kb, g_K);
    cudaGetSymbolAddress((void**)&Vb, g_V);
    cudaGetSymbolAddress((void**)&Hb, g_Hh);
    cudaGetSymbolAddress((void**)&Yb, g_Y);

    cudaFuncSetAttribute(attn_mma_kernel, cudaFuncAttributeMaxDynamicSharedMemorySize, ATTN_SMEM_BYTES);

    dim3 ggrid(Dd / GBN, Mm / GBM);   // (8, 64)
    gemm_mma_kernel<<<ggrid, 256>>>(x, Wq, bq, nullptr, Qb, Mm, Dd, Dd);
    gemm_mma_kernel<<<ggrid, 256>>>(x, Wk, bk, nullptr, Kb, Mm, Dd, Dd);
    gemm_mma_kernel<<<ggrid, 256>>>(x, Wv, bv, nullptr, Vb, Mm, Dd, Dd);

    dim3 agrid(Nn / 64, Hh, Bb);      // (32, 8, 4)
    attn_mma_kernel<<<agrid, 128, ATTN_SMEM_BYTES>>>(Qb, Kb, Vb, adj, Hb);

    gemm_mma_kernel<<<ggrid, 256>>>(Hb, Wo, bo, x, Yb, Mm, Dd, Dd);

    ln_kernel<<<Mm, 128>>>(Yb, gamma, beta, out);
}

// round 9
// speedup vs baseline: 1.4886x; 1.1151x over previous
#include <cuda_runtime.h>
#include <cstdint>
#include <math.h>

#define Bb 4
#define Nn 2048
#define Dd 512
#define Hh 8
#define HD 64
#define Mm (Bb * Nn)   // 8192
#define SC_LOG2E 0.18033688f   // 0.125 * log2(e)

// ---------------- scratch ----------------
__device__ float g_Q[(size_t)Mm * Dd];
__device__ float g_K[(size_t)Mm * Dd];
__device__ float g_V[(size_t)Mm * Dd];
__device__ float g_Hh[(size_t)Mm * Dd];
__device__ float g_Y[(size_t)Mm * Dd];

// ---------------- helpers ----------------
__device__ __forceinline__ float ex2(float x) {
    float y; asm("ex2.approx.f32 %0, %1;" : "=f"(y) : "f"(x)); return y;
}
__device__ __forceinline__ float tf32r(float f) {
    uint32_t u; asm("cvt.rna.tf32.f32 %0, %1;" : "=r"(u) : "f"(f));
    return __uint_as_float(u);
}
__device__ __forceinline__ float4 tf32r4(float4 v) {
    v.x = tf32r(v.x); v.y = tf32r(v.y); v.z = tf32r(v.z); v.w = tf32r(v.w);
    return v;
}
__device__ __forceinline__ void mma_tf32(float* c, const uint32_t* a, const uint32_t* b) {
    asm volatile("mma.sync.aligned.m16n8k8.row.col.f32.tf32.tf32.f32 "
        "{%0,%1,%2,%3}, {%4,%5,%6,%7}, {%8,%9}, {%0,%1,%2,%3};"
        : "+f"(c[0]), "+f"(c[1]), "+f"(c[2]), "+f"(c[3])
        : "r"(a[0]), "r"(a[1]), "r"(a[2]), "r"(a[3]), "r"(b[0]), "r"(b[1]));
}

// ======================================================================
// tf32 mma GEMM (R5 structure, float4 staging stores)
// BM=128, BN=64, BK=32, 256 threads (8 warps 4x2), warp tile 32x32.
// ======================================================================
#define GBM 128
#define GBN 64
#define GBK 32
#define ASTR 36
#define BSTR 68

__global__ void __launch_bounds__(256, 3) gemm_mma_kernel(
    const float* __restrict__ A, const float* __restrict__ W,
    const float* __restrict__ bias, const float* __restrict__ resid,
    float* __restrict__ C, int M, int N, int K)
{
    __shared__ __align__(16) float As[GBM * ASTR];   // [m][k]
    __shared__ __align__(16) float Ws[GBK * BSTR];   // [k][n]

    const int tid = threadIdx.x;
    const int wid = tid >> 5, lane = tid & 31;
    const int g = lane >> 2, q = lane & 3;
    const int wm = wid & 3, wn = wid >> 2;
    const int m0 = blockIdx.y * GBM;
    const int n0 = blockIdx.x * GBN;

    float acc[2][4][4];
#pragma unroll
    for (int t = 0; t < 2; t++)
#pragma unroll
        for (int nb = 0; nb < 4; nb++)
#pragma unroll
            for (int i = 0; i < 4; i++) acc[t][nb][i] = 0.f;

    for (int k0 = 0; k0 < K; k0 += GBK) {
#pragma unroll
        for (int i = 0; i < 4; i++) {
            int idx = i * 256 + tid;
            int r = idx >> 3, c4 = (idx & 7) * 4;
            float4 a4 = tf32r4(*(const float4*)(A + (size_t)(m0 + r) * K + k0 + c4));
            *(float4*)(As + r * ASTR + c4) = a4;
        }
#pragma unroll
        for (int i = 0; i < 2; i++) {
            int idx = i * 256 + tid;
            int r = idx >> 4, c4 = (idx & 15) * 4;
            float4 w4 = tf32r4(*(const float4*)(W + (size_t)(k0 + r) * N + n0 + c4));
            *(float4*)(Ws + r * BSTR + c4) = w4;
        }
        __syncthreads();

#pragma unroll
        for (int kk = 0; kk < 4; kk++) {
            uint32_t a[2][4];
#pragma unroll
            for (int t = 0; t < 2; t++) {
                const float* ar = As + (wm * 32 + 16 * t + g) * ASTR + 8 * kk + q;
                a[t][0] = __float_as_uint(ar[0]);
                a[t][1] = __float_as_uint(ar[8 * ASTR]);
                a[t][2] = __float_as_uint(ar[4]);
                a[t][3] = __float_as_uint(ar[8 * ASTR + 4]);
            }
            uint32_t bf[4][2];
#pragma unroll
            for (int nb = 0; nb < 4; nb++) {
                const float* br = Ws + (8 * kk + q) * BSTR + wn * 32 + 8 * nb + g;
                bf[nb][0] = __float_as_uint(br[0]);
                bf[nb][1] = __float_as_uint(br[4 * BSTR]);
            }
#pragma unroll
            for (int t = 0; t < 2; t++)
#pragma unroll
                for (int nb = 0; nb < 4; nb++)
                    mma_tf32(acc[t][nb], a[t], bf[nb]);
        }
        __syncthreads();
    }

#pragma unroll
    for (int t = 0; t < 2; t++) {
        const int r0 = m0 + wm * 32 + 16 * t + g;
#pragma unroll
        for (int nb = 0; nb < 4; nb++) {
            const int c = n0 + wn * 32 + 8 * nb + 2 * q;
            float bx = bias[c], by = bias[c + 1];
            float2 w0, w1;
            w0.x = acc[t][nb][0] + bx; w0.y = acc[t][nb][1] + by;
            w1.x = acc[t][nb][2] + bx; w1.y = acc[t][nb][3] + by;
            if (resid) {
                float2 r4 = *(const float2*)(resid + (size_t)r0 * N + c);
                float2 r5 = *(const float2*)(resid + (size_t)(r0 + 8) * N + c);
                w0.x += r4.x; w0.y += r4.y;
                w1.x += r5.x; w1.y += r5.y;
            }
            *(float2*)(C + (size_t)r0 * N + c) = w0;
            *(float2*)(C + (size_t)(r0 + 8) * N + c) = w1;
        }
    }
}

// ======================================================================
// mma.sync tf32 attention: 128 queries/CTA, 256 threads (8 warps),
// 16 queries/warp, target 2 CTAs/SM (16 warps).
// grid (16 q-tiles, 8 heads, 4 batch).
// ======================================================================
#define STR 68
#define OFF_Q 0
#define OFF_K (128 * STR)
#define OFF_V (192 * STR)
#define OFF_P (256 * STR)
#define ATTN_SMEM_FLOATS (384 * STR)            // 26112
#define ATTN_SMEM_BYTES (ATTN_SMEM_FLOATS * 4)  // 104448

__global__ void __launch_bounds__(256, 2) attn_mma_kernel(
    const float* __restrict__ Q, const float* __restrict__ K,
    const float* __restrict__ V, const int* __restrict__ adj,
    float* __restrict__ O)
{
    extern __shared__ __align__(16) float sm[];
    const int tid = threadIdx.x;
    const int wid = tid >> 5, lane = tid & 31;
    const int g = lane >> 2, q = lane & 3;
    const int h = blockIdx.y, b = blockIdx.z;
    const int q0 = blockIdx.x * 128;
    const unsigned FULL = 0xffffffffu;

    // ---- stage Q tile (128 x 64), tf32-rounded, float4 stores ----
    {
        const float* qg = Q + ((size_t)(b * Nn + q0)) * Dd + h * HD;
#pragma unroll
        for (int i = 0; i < 8; i++) {
            int f = i * 256 + tid, r = f >> 4, c = (f & 15) * 4;
            float4 v4 = tf32r4(*(const float4*)(qg + (size_t)r * Dd + c));
            *(float4*)(sm + OFF_Q + r * STR + c) = v4;
        }
    }
    __syncthreads();

    float oacc[8][4];
#pragma unroll
    for (int n = 0; n < 8; n++)
#pragma unroll
        for (int i = 0; i < 4; i++) oacc[n][i] = 0.f;
    float lacc[2] = {0.f, 0.f};   // rows g, g+8 of the warp's 16-row tile

    float* Pw = sm + OFF_P + wid * 16 * STR;
    const float* Ks = sm + OFF_K;
    const float* Vs = sm + OFF_V;

#pragma unroll 1
    for (int t64 = 0; t64 < 32; t64++) {
        const int k0 = t64 * 64;
        __syncthreads();
        // ---- stage K, V tiles (64 x 64), tf32-rounded, float4 stores ----
        {
            const float* kg = K + ((size_t)(b * Nn + k0)) * Dd + h * HD;
            const float* vg = V + ((size_t)(b * Nn + k0)) * Dd + h * HD;
#pragma unroll
            for (int i = 0; i < 4; i++) {
                int f = i * 256 + tid, r = f >> 4, c = (f & 15) * 4;
                float4 kv = tf32r4(*(const float4*)(kg + (size_t)r * Dd + c));
                *(float4*)(sm + OFF_K + r * STR + c) = kv;
                float4 vv = tf32r4(*(const float4*)(vg + (size_t)r * Dd + c));
                *(float4*)(sm + OFF_V + r * STR + c) = vv;
            }
        }
        __syncthreads();

        // ---- S = Q(16x64) @ K^T(64x64) per warp: 64 mma ----
        float sacc[8][4];
#pragma unroll
        for (int n = 0; n < 8; n++)
#pragma unroll
            for (int i = 0; i < 4; i++) sacc[n][i] = 0.f;

#pragma unroll
        for (int kk = 0; kk < 8; kk++) {
            uint32_t a[4];
            {
                const float* qrow = sm + OFF_Q + (wid * 16 + g) * STR + 8 * kk + q;
                a[0] = __float_as_uint(qrow[0]);
                a[1] = __float_as_uint(qrow[8 * STR]);
                a[2] = __float_as_uint(qrow[4]);
                a[3] = __float_as_uint(qrow[8 * STR + 4]);
            }
            uint32_t bf[8][2];
#pragma unroll
            for (int n = 0; n < 8; n++) {
                const float* krow = Ks + (8 * n + g) * STR + 8 * kk + q;
                bf[n][0] = __float_as_uint(krow[0]);
                bf[n][1] = __float_as_uint(krow[4]);
            }
#pragma unroll
            for (int n = 0; n < 8; n++)
                mma_tf32(sacc[n], a, bf[n]);
        }

        // ---- softmax: P = mask * exp2(S*sc); row sums; store P to SMEM ----
        {
            const size_t arow = (size_t)(b * Nn + q0 + wid * 16 + g) * Nn + k0;
            const int* a0p = adj + arow;                     // row g
            const int* a1p = adj + arow + (size_t)8 * Nn;    // row g+8
            float l0 = 0.f, l1 = 0.f;
#pragma unroll
            for (int n = 0; n < 8; n++) {
                int2 m0 = *(const int2*)(a0p + 8 * n + 2 * q);
                int2 m1 = *(const int2*)(a1p + 8 * n + 2 * q);
                float p0 = m0.x ? ex2(sacc[n][0] * SC_LOG2E) : 0.f;
                float p1 = m0.y ? ex2(sacc[n][1] * SC_LOG2E) : 0.f;
                float p2 = m1.x ? ex2(sacc[n][2] * SC_LOG2E) : 0.f;
                float p3 = m1.y ? ex2(sacc[n][3] * SC_LOG2E) : 0.f;
                l0 += p0 + p1; l1 += p2 + p3;
                float2 w0; w0.x = tf32r(p0); w0.y = tf32r(p1);
                float2 w1; w1.x = tf32r(p2); w1.y = tf32r(p3);
                *(float2*)(Pw + g * STR + 8 * n + 2 * q) = w0;
                *(float2*)(Pw + (g + 8) * STR + 8 * n + 2 * q) = w1;
            }
            lacc[0] += l0;
            lacc[1] += l1;
        }
        __syncwarp();

        // ---- O += P(16x64) @ V(64x64): 64 mma ----
#pragma unroll
        for (int kk = 0; kk < 8; kk++) {
            uint32_t a[4];
            {
                const float* prow = Pw + g * STR + 8 * kk + q;
                a[0] = __float_as_uint(prow[0]);
                a[1] = __float_as_uint(prow[8 * STR]);
                a[2] = __float_as_uint(prow[4]);
                a[3] = __float_as_uint(prow[8 * STR + 4]);
            }
            uint32_t bf[8][2];
#pragma unroll
            for (int n = 0; n < 8; n++) {
                const float* vrow = Vs + (8 * kk + q) * STR + 8 * n + g;
                bf[n][0] = __float_as_uint(vrow[0]);
                bf[n][1] = __float_as_uint(vrow[4 * STR]);
            }
#pragma unroll
            for (int n = 0; n < 8; n++)
                mma_tf32(oacc[n], a, bf[n]);
        }
        __syncwarp();
    }

    // ---- reduce row sums across the quad (lanes sharing g) ----
#pragma unroll
    for (int i = 0; i < 2; i++) {
        lacc[i] += __shfl_xor_sync(FULL, lacc[i], 1);
        lacc[i] += __shfl_xor_sync(FULL, lacc[i], 2);
    }
    const float inv0 = 1.f / lacc[0];
    const float inv1 = 1.f / lacc[1];

    // ---- write O ----
    float* og = O + ((size_t)(b * Nn + q0 + wid * 16)) * Dd + h * HD;
#pragma unroll
    for (int n = 0; n < 8; n++) {
        float2 w0;
        w0.x = oacc[n][0] * inv0;
        w0.y = oacc[n][1] * inv0;
        *(float2*)(og + (size_t)g * Dd + 8 * n + 2 * q) = w0;
        float2 w1;
        w1.x = oacc[n][2] * inv1;
        w1.y = oacc[n][3] * inv1;
        *(float2*)(og + (size_t)(g + 8) * Dd + 8 * n + 2 * q) = w1;
    }
}

// ================= LayerNorm (unchanged) =================
__global__ __launch_bounds__(128) void ln_kernel(
    const float* __restrict__ Y, const float* __restrict__ gamma,
    const float* __restrict__ beta, float* __restrict__ out)
{
    __shared__ float sbuf[4];
    __shared__ float smu, srstd;
    const int tid = threadIdx.x;
    const int row = blockIdx.x;
    const float* y = Y + (size_t)row * Dd;

    float4 v = ((const float4*)y)[tid];
    float sum = v.x + v.y + v.z + v.w;
    int lane = tid & 31, wid = tid >> 5;
#pragma unroll
    for (int off = 16; off > 0; off >>= 1) sum += __shfl_xor_sync(0xffffffffu, sum, off);
    if (lane == 0) sbuf[wid] = sum;
    __syncthreads();
    if (tid == 0) smu = (sbuf[0] + sbuf[1] + sbuf[2] + sbuf[3]) * (1.f / Dd);
    __syncthreads();
    float mu = smu;

    float dx = v.x - mu, dy = v.y - mu, dz = v.z - mu, dw = v.w - mu;
    float sq = dx * dx + dy * dy + dz * dz + dw * dw;
#pragma unroll
    for (int off = 16; off > 0; off >>= 1) sq += __shfl_xor_sync(0xffffffffu, sq, off);
    __syncthreads();
    if (lane == 0) sbuf[wid] = sq;
    __syncthreads();
    if (tid == 0) {
        float var = (sbuf[0] + sbuf[1] + sbuf[2] + sbuf[3]) * (1.f / Dd);
        srstd = rsqrtf(var + 1e-5f);
    }
    __syncthreads();
    float rstd = srstd;

    int c = tid * 4;
    float4 g = *(const float4*)(gamma + c);
    float4 be = *(const float4*)(beta + c);
    float4 r;
    r.x = dx * rstd * g.x + be.x;
    r.y = dy * rstd * g.y + be.y;
    r.z = dz * rstd * g.z + be.z;
    r.w = dw * rstd * g.w + be.w;
    ((float4*)(out + (size_t)row * Dd))[tid] = r;
}

// ================= launch =================
extern "C" void kernel_launch(void* const* d_in, const int* in_sizes, int n_in,
                              void* d_out, int out_size)
{
    const float* x     = (const float*)d_in[0];
    const int*   adj   = (const int*)d_in[1];
    const float* Wq    = (const float*)d_in[2];
    const float* bq    = (const float*)d_in[3];
    const float* Wk    = (const float*)d_in[4];
    const float* bk    = (const float*)d_in[5];
    const float* Wv    = (const float*)d_in[6];
    const float* bv    = (const float*)d_in[7];
    const float* Wo    = (const float*)d_in[8];
    const float* bo    = (const float*)d_in[9];
    const float* gamma = (const float*)d_in[10];
    const float* beta  = (const float*)d_in[11];
    float* out = (float*)d_out;

    float *Qb, *Kb, *Vb, *Hb, *Yb;
    cudaGetSymbolAddress((void**)&Qb, g_Q);
    cudaGetSymbolAddress((void**)&Kb, g_K);
    cudaGetSymbolAddress((void**)&Vb, g_V);
    cudaGetSymbolAddress((void**)&Hb, g_Hh);
    cudaGetSymbolAddress((void**)&Yb, g_Y);

    cudaFuncSetAttribute(attn_mma_kernel, cudaFuncAttributeMaxDynamicSharedMemorySize, ATTN_SMEM_BYTES);

    dim3 ggrid(Dd / GBN, Mm / GBM);   // (8, 64)
    gemm_mma_kernel<<<ggrid, 256>>>(x, Wq, bq, nullptr, Qb, Mm, Dd, Dd);
    gemm_mma_kernel<<<ggrid, 256>>>(x, Wk, bk, nullptr, Kb, Mm, Dd, Dd);
    gemm_mma_kernel<<<ggrid, 256>>>(x, Wv, bv, nullptr, Vb, Mm, Dd, Dd);

    dim3 agrid(Nn / 128, Hh, Bb);     // (16, 8, 4)
    attn_mma_kernel<<<agrid, 256, ATTN_SMEM_BYTES>>>(Qb, Kb, Vb, adj, Hb);

    gemm_mma_kernel<<<ggrid, 256>>>(Hb, Wo, bo, x, Yb, Mm, Dd, Dd);

    ln_kernel<<<Mm, 128>>>(Yb, gamma, beta, out);
}